// round 4
// baseline (speedup 1.0000x reference)
#include <cuda_runtime.h>
#include <cuda_bf16.h>
#include <cstdint>
#include <cstddef>

// Problem shape (fixed by the reference): D = K = 128.
#define TM   128        // rows per tile
#define DK   128        // feature dim
#define KK   128        // codebook size
#define WTS  132        // padded stride for transposed W in smem
#define NT   256        // threads per CTA

// Dynamic smem layout (floats):
//   Abuf : 2 * TM * DK          (double-buffered A tile)
//   Wt   : DK * WTS             (W transposed, d-major, padded)
//   c2   : KK                   (||w_k||^2)
//   best : TM ints
static constexpr int SMEM_BYTES =
    (2 * TM * DK + DK * WTS + KK) * 4 + TM * 4;   // 199,680 B <= 227 KB

__device__ __forceinline__ void cp_async16(void* smem_dst, const void* gsrc) {
    uint32_t s = (uint32_t)__cvta_generic_to_shared(smem_dst);
    asm volatile("cp.async.cg.shared.global [%0], [%1], 16;\n" :: "r"(s), "l"(gsrc));
}
__device__ __forceinline__ void cp_commit() {
    asm volatile("cp.async.commit_group;\n");
}

__global__ __launch_bounds__(NT, 1)
void vq_kernel(const float* __restrict__ A, const float* __restrict__ W,
               float* __restrict__ out, int N, int ntiles) {
    extern __shared__ float sm[];
    float* Abuf = sm;                       // 2*TM*DK
    float* Wt   = sm + 2 * TM * DK;         // DK*WTS
    float* c2   = Wt + DK * WTS;            // KK
    int*   best = (int*)(c2 + KK);          // TM

    const int tid = threadIdx.x;
    const int tx  = tid & 15;               // 16 k-groups of 8
    const int ty  = tid >> 4;               // 16 row-groups of 8

    // ---- prologue: prefetch first tile into buf 0 ----
    const int t0 = blockIdx.x;
    if (t0 < ntiles) {
        for (int i = tid; i < TM * DK / 4; i += NT) {
            int r = i >> 5, f4 = i & 31;
            int gr = t0 * TM + r; if (gr >= N) gr = N - 1;
            cp_async16(&Abuf[r * DK + f4 * 4], &A[(size_t)gr * DK + f4 * 4]);
        }
    }
    cp_commit();

    // ---- transpose W into smem (one-time) ----
    const float4* W4 = (const float4*)W;
    for (int i = tid; i < KK * DK / 4; i += NT) {
        int k = i >> 5, f4 = i & 31;
        float4 v = W4[i];
        int d = f4 * 4;
        Wt[(d + 0) * WTS + k] = v.x;
        Wt[(d + 1) * WTS + k] = v.y;
        Wt[(d + 2) * WTS + k] = v.z;
        Wt[(d + 3) * WTS + k] = v.w;
    }
    // ---- ||w_k||^2 ----
    if (tid < KK) {
        float s = 0.f;
        const float* wr = W + (size_t)tid * DK;
        #pragma unroll 8
        for (int d = 0; d < DK; d++) s = fmaf(wr[d], wr[d], s);
        c2[tid] = s;
    }
    __syncthreads();

    float c2k[8];
    #pragma unroll
    for (int j = 0; j < 8; j++) c2k[j] = c2[tx * 8 + j];

    const float4* Wg4    = (const float4*)W;
    float4*       O      = (float4*)out;
    const size_t  embOff = (size_t)N * 32;   // second output half, in float4 units

    int buf = 0;
    for (int t = blockIdx.x; t < ntiles; t += gridDim.x) {
        // prefetch next tile, then wait for current
        const int tn = t + gridDim.x;
        if (tn < ntiles) {
            float* dst = Abuf + (buf ^ 1) * TM * DK;
            for (int i = tid; i < TM * DK / 4; i += NT) {
                int r = i >> 5, f4 = i & 31;
                int gr = tn * TM + r; if (gr >= N) gr = N - 1;
                cp_async16(&dst[r * DK + f4 * 4], &A[(size_t)gr * DK + f4 * 4]);
            }
            cp_commit();
            asm volatile("cp.async.wait_group 1;\n");
        } else {
            asm volatile("cp.async.wait_group 0;\n");
        }
        __syncthreads();

        // ---- 128x128 fp32 GEMM tile, 8x8 register blocking ----
        const float* Ab = Abuf + buf * TM * DK + (ty * 8) * DK;
        float acc[8][8];
        #pragma unroll
        for (int i = 0; i < 8; i++)
            #pragma unroll
            for (int j = 0; j < 8; j++) acc[i][j] = 0.f;

        #pragma unroll 2
        for (int d = 0; d < DK; d += 4) {
            float4 av[8];
            #pragma unroll
            for (int i = 0; i < 8; i++)
                av[i] = *(const float4*)&Ab[i * DK + d];
            #pragma unroll
            for (int dd = 0; dd < 4; dd++) {
                const float4 b0 = *(const float4*)&Wt[(d + dd) * WTS + tx * 8];
                const float4 b1 = *(const float4*)&Wt[(d + dd) * WTS + tx * 8 + 4];
                const float b[8] = {b0.x, b0.y, b0.z, b0.w, b1.x, b1.y, b1.z, b1.w};
                #pragma unroll
                for (int i = 0; i < 8; i++) {
                    const float a = (dd == 0) ? av[i].x : (dd == 1) ? av[i].y
                                  : (dd == 2) ? av[i].z : av[i].w;
                    #pragma unroll
                    for (int j = 0; j < 8; j++)
                        acc[i][j] = fmaf(a, b[j], acc[i][j]);
                }
            }
        }

        // ---- per-row argmin of (||w||^2 - 2 x.w), lowest-index tie-break ----
        #pragma unroll
        for (int i = 0; i < 8; i++) {
            float bv = fmaf(-2.f, acc[i][0], c2k[0]);
            int   bk = tx * 8;
            #pragma unroll
            for (int j = 1; j < 8; j++) {
                float v = fmaf(-2.f, acc[i][j], c2k[j]);
                if (v < bv) { bv = v; bk = tx * 8 + j; }
            }
            #pragma unroll
            for (int off = 1; off < 16; off <<= 1) {
                float ov = __shfl_xor_sync(0xffffffffu, bv, off);
                int   ok = __shfl_xor_sync(0xffffffffu, bk, off);
                if (ov < bv || (ov == bv && ok < bk)) { bv = ov; bk = ok; }
            }
            if (tx == 0) best[ty * 8 + i] = bk;
        }
        __syncthreads();

        // ---- gather W[best] and write both halves (z_q, emb) ----
        for (int i = tid; i < TM * 32; i += NT) {
            int r = i >> 5, f4 = i & 31;
            int gr = t * TM + r;
            if (gr < N) {
                int k = best[r];
                float4 v = Wg4[k * 32 + f4];
                O[(size_t)gr * 32 + f4]          = v;
                O[embOff + (size_t)gr * 32 + f4] = v;
            }
        }
        buf ^= 1;
        // next iteration's post-wait __syncthreads orders this output phase
        // against best[] overwrite; cp.async overwrite of 'buf^1' is ordered
        // by the pre-argmin sync two iterations back.
    }
}

extern "C" void kernel_launch(void* const* d_in, const int* in_sizes, int n_in,
                              void* d_out, int out_size) {
    const float* A = (const float*)d_in[0];
    const float* W = (const float*)d_in[1];
    int szA = in_sizes[0], szW = in_sizes[1];
    // Defensive: metadata order should be (z_g, W); swap if reversed.
    if (n_in >= 2 && szA < szW) {
        const float* tmp = A; A = W; W = tmp;
        int ts = szA; szA = szW; szW = ts;
    }
    const int N      = szA / DK;
    const int ntiles = (N + TM - 1) / TM;

    int dev = 0, sms = 148;
    cudaGetDevice(&dev);
    cudaDeviceGetAttribute(&sms, cudaDevAttrMultiProcessorCount, dev);

    cudaFuncSetAttribute(vq_kernel, cudaFuncAttributeMaxDynamicSharedMemorySize,
                         SMEM_BYTES);

    int grid = ntiles < sms ? ntiles : sms;
    vq_kernel<<<grid, NT, SMEM_BYTES>>>(A, W, (float*)d_out, N, ntiles);
}

// round 5
// speedup vs baseline: 1.0013x; 1.0013x over previous
#include <cuda_runtime.h>
#include <cuda_bf16.h>
#include <cstdint>
#include <cstddef>

// Problem shape (fixed by the reference): D = K = 128.
#define TM   128        // rows per tile
#define DK   128        // feature dim
#define KK   128        // codebook size
#define WTS  132        // padded stride for transposed W in smem
#define NT   256        // threads per CTA

// Dynamic smem layout (floats):
//   Abuf : 2 * TM * DK          (double-buffered A tile)
//   Wt   : DK * WTS             (W transposed, d-major, padded)
//   c2   : KK                   (||w_k||^2)
//   best : TM ints
static constexpr int SMEM_BYTES =
    (2 * TM * DK + DK * WTS + KK) * 4 + TM * 4;   // 199,680 B <= 227 KB

__device__ __forceinline__ void cp_async16(void* smem_dst, const void* gsrc) {
    uint32_t s = (uint32_t)__cvta_generic_to_shared(smem_dst);
    asm volatile("cp.async.cg.shared.global [%0], [%1], 16;\n" :: "r"(s), "l"(gsrc));
}
__device__ __forceinline__ void cp_commit() {
    asm volatile("cp.async.commit_group;\n");
}

__global__ __launch_bounds__(NT, 1)
void vq_kernel(const float* __restrict__ A, const float* __restrict__ W,
               float* __restrict__ out, int N, int ntiles) {
    extern __shared__ float sm[];
    float* Abuf = sm;                       // 2*TM*DK
    float* Wt   = sm + 2 * TM * DK;         // DK*WTS
    float* c2   = Wt + DK * WTS;            // KK
    int*   best = (int*)(c2 + KK);          // TM

    const int tid = threadIdx.x;
    const int tx  = tid & 15;               // 16 k-groups of 8
    const int ty  = tid >> 4;               // 16 row-groups of 8

    // ---- prologue: prefetch first tile into buf 0 ----
    const int t0 = blockIdx.x;
    if (t0 < ntiles) {
        for (int i = tid; i < TM * DK / 4; i += NT) {
            int r = i >> 5, f4 = i & 31;
            int gr = t0 * TM + r; if (gr >= N) gr = N - 1;
            cp_async16(&Abuf[r * DK + f4 * 4], &A[(size_t)gr * DK + f4 * 4]);
        }
    }
    cp_commit();

    // ---- transpose W into smem (one-time) ----
    const float4* W4 = (const float4*)W;
    for (int i = tid; i < KK * DK / 4; i += NT) {
        int k = i >> 5, f4 = i & 31;
        float4 v = W4[i];
        int d = f4 * 4;
        Wt[(d + 0) * WTS + k] = v.x;
        Wt[(d + 1) * WTS + k] = v.y;
        Wt[(d + 2) * WTS + k] = v.z;
        Wt[(d + 3) * WTS + k] = v.w;
    }
    // ---- ||w_k||^2 ----
    if (tid < KK) {
        float s = 0.f;
        const float* wr = W + (size_t)tid * DK;
        #pragma unroll 8
        for (int d = 0; d < DK; d++) s = fmaf(wr[d], wr[d], s);
        c2[tid] = s;
    }
    __syncthreads();

    float c2k[8];
    #pragma unroll
    for (int j = 0; j < 8; j++) c2k[j] = c2[tx * 8 + j];

    const float4* Wg4    = (const float4*)W;
    float4*       O      = (float4*)out;
    const size_t  embOff = (size_t)N * 32;   // second output half, in float4 units

    int buf = 0;
    for (int t = blockIdx.x; t < ntiles; t += gridDim.x) {
        // prefetch next tile, then wait for current
        const int tn = t + gridDim.x;
        if (tn < ntiles) {
            float* dst = Abuf + (buf ^ 1) * TM * DK;
            for (int i = tid; i < TM * DK / 4; i += NT) {
                int r = i >> 5, f4 = i & 31;
                int gr = tn * TM + r; if (gr >= N) gr = N - 1;
                cp_async16(&dst[r * DK + f4 * 4], &A[(size_t)gr * DK + f4 * 4]);
            }
            cp_commit();
            asm volatile("cp.async.wait_group 1;\n");
        } else {
            asm volatile("cp.async.wait_group 0;\n");
        }
        __syncthreads();

        // ---- 128x128 fp32 GEMM tile, 8x8 register blocking ----
        const float* Ab = Abuf + buf * TM * DK + (ty * 8) * DK;
        float acc[8][8];
        #pragma unroll
        for (int i = 0; i < 8; i++)
            #pragma unroll
            for (int j = 0; j < 8; j++) acc[i][j] = 0.f;

        #pragma unroll 2
        for (int d = 0; d < DK; d += 4) {
            float4 av[8];
            #pragma unroll
            for (int i = 0; i < 8; i++)
                av[i] = *(const float4*)&Ab[i * DK + d];
            #pragma unroll
            for (int dd = 0; dd < 4; dd++) {
                const float4 b0 = *(const float4*)&Wt[(d + dd) * WTS + tx * 8];
                const float4 b1 = *(const float4*)&Wt[(d + dd) * WTS + tx * 8 + 4];
                const float b[8] = {b0.x, b0.y, b0.z, b0.w, b1.x, b1.y, b1.z, b1.w};
                #pragma unroll
                for (int i = 0; i < 8; i++) {
                    const float a = (dd == 0) ? av[i].x : (dd == 1) ? av[i].y
                                  : (dd == 2) ? av[i].z : av[i].w;
                    #pragma unroll
                    for (int j = 0; j < 8; j++)
                        acc[i][j] = fmaf(a, b[j], acc[i][j]);
                }
            }
        }

        // ---- per-row argmin of (||w||^2 - 2 x.w), lowest-index tie-break ----
        #pragma unroll
        for (int i = 0; i < 8; i++) {
            float bv = fmaf(-2.f, acc[i][0], c2k[0]);
            int   bk = tx * 8;
            #pragma unroll
            for (int j = 1; j < 8; j++) {
                float v = fmaf(-2.f, acc[i][j], c2k[j]);
                if (v < bv) { bv = v; bk = tx * 8 + j; }
            }
            #pragma unroll
            for (int off = 1; off < 16; off <<= 1) {
                float ov = __shfl_xor_sync(0xffffffffu, bv, off);
                int   ok = __shfl_xor_sync(0xffffffffu, bk, off);
                if (ov < bv || (ov == bv && ok < bk)) { bv = ov; bk = ok; }
            }
            if (tx == 0) best[ty * 8 + i] = bk;
        }
        __syncthreads();

        // ---- gather W[best] and write both halves (z_q, emb) ----
        for (int i = tid; i < TM * 32; i += NT) {
            int r = i >> 5, f4 = i & 31;
            int gr = t * TM + r;
            if (gr < N) {
                int k = best[r];
                float4 v = Wg4[k * 32 + f4];
                O[(size_t)gr * 32 + f4]          = v;
                O[embOff + (size_t)gr * 32 + f4] = v;
            }
        }
        buf ^= 1;
        // next iteration's post-wait __syncthreads orders this output phase
        // against best[] overwrite; cp.async overwrite of 'buf^1' is ordered
        // by the pre-argmin sync two iterations back.
    }
}

extern "C" void kernel_launch(void* const* d_in, const int* in_sizes, int n_in,
                              void* d_out, int out_size) {
    const float* A = (const float*)d_in[0];
    const float* W = (const float*)d_in[1];
    int szA = in_sizes[0], szW = in_sizes[1];
    // Defensive: metadata order should be (z_g, W); swap if reversed.
    if (n_in >= 2 && szA < szW) {
        const float* tmp = A; A = W; W = tmp;
        int ts = szA; szA = szW; szW = ts;
    }
    const int N      = szA / DK;
    const int ntiles = (N + TM - 1) / TM;

    int dev = 0, sms = 148;
    cudaGetDevice(&dev);
    cudaDeviceGetAttribute(&sms, cudaDevAttrMultiProcessorCount, dev);

    cudaFuncSetAttribute(vq_kernel, cudaFuncAttributeMaxDynamicSharedMemorySize,
                         SMEM_BYTES);

    int grid = ntiles < sms ? ntiles : sms;
    vq_kernel<<<grid, NT, SMEM_BYTES>>>(A, W, (float*)d_out, N, ntiles);
}

// round 6
// speedup vs baseline: 1.0045x; 1.0032x over previous
#include <cuda_runtime.h>
#include <cuda_bf16.h>
#include <cstdint>
#include <cstddef>

// Problem shape (fixed by the reference): D = K = 128.
#define TM   128        // rows per tile
#define DK   128        // feature dim
#define KK   128        // codebook size
#define WTS  132        // padded stride for transposed W in smem
#define NT   256        // threads per CTA

// Dynamic smem layout (floats):
//   Abuf : 2 * TM * DK          (double-buffered A tile)
//   Wt   : DK * WTS             (W transposed, d-major, padded)
//   c2   : KK                   (||w_k||^2)
//   best : TM ints
static constexpr int SMEM_BYTES =
    (2 * TM * DK + DK * WTS + KK) * 4 + TM * 4;   // 199,680 B <= 227 KB

__device__ __forceinline__ void cp_async16(void* smem_dst, const void* gsrc) {
    uint32_t s = (uint32_t)__cvta_generic_to_shared(smem_dst);
    asm volatile("cp.async.cg.shared.global [%0], [%1], 16;\n" :: "r"(s), "l"(gsrc));
}
__device__ __forceinline__ void cp_commit() {
    asm volatile("cp.async.commit_group;\n");
}

__global__ __launch_bounds__(NT, 1)
void vq_kernel(const float* __restrict__ A, const float* __restrict__ W,
               float* __restrict__ out, int N, int ntiles) {
    extern __shared__ float sm[];
    float* Abuf = sm;                       // 2*TM*DK
    float* Wt   = sm + 2 * TM * DK;         // DK*WTS
    float* c2   = Wt + DK * WTS;            // KK
    int*   best = (int*)(c2 + KK);          // TM

    const int tid = threadIdx.x;
    const int tx  = tid & 15;               // 16 k-groups of 8
    const int ty  = tid >> 4;               // 16 row-groups of 8

    // ---- prologue: prefetch first tile into buf 0 ----
    const int t0 = blockIdx.x;
    if (t0 < ntiles) {
        for (int i = tid; i < TM * DK / 4; i += NT) {
            int r = i >> 5, f4 = i & 31;
            int gr = t0 * TM + r; if (gr >= N) gr = N - 1;
            cp_async16(&Abuf[r * DK + f4 * 4], &A[(size_t)gr * DK + f4 * 4]);
        }
    }
    cp_commit();

    // ---- transpose W into smem (one-time) ----
    const float4* W4 = (const float4*)W;
    for (int i = tid; i < KK * DK / 4; i += NT) {
        int k = i >> 5, f4 = i & 31;
        float4 v = W4[i];
        int d = f4 * 4;
        Wt[(d + 0) * WTS + k] = v.x;
        Wt[(d + 1) * WTS + k] = v.y;
        Wt[(d + 2) * WTS + k] = v.z;
        Wt[(d + 3) * WTS + k] = v.w;
    }
    // ---- ||w_k||^2 ----
    if (tid < KK) {
        float s = 0.f;
        const float* wr = W + (size_t)tid * DK;
        #pragma unroll 8
        for (int d = 0; d < DK; d++) s = fmaf(wr[d], wr[d], s);
        c2[tid] = s;
    }
    __syncthreads();

    float c2k[8];
    #pragma unroll
    for (int j = 0; j < 8; j++) c2k[j] = c2[tx * 8 + j];

    const float4* Wg4    = (const float4*)W;
    float4*       O      = (float4*)out;
    const size_t  embOff = (size_t)N * 32;   // second output half, in float4 units

    int buf = 0;
    for (int t = blockIdx.x; t < ntiles; t += gridDim.x) {
        // prefetch next tile, then wait for current
        const int tn = t + gridDim.x;
        if (tn < ntiles) {
            float* dst = Abuf + (buf ^ 1) * TM * DK;
            for (int i = tid; i < TM * DK / 4; i += NT) {
                int r = i >> 5, f4 = i & 31;
                int gr = tn * TM + r; if (gr >= N) gr = N - 1;
                cp_async16(&dst[r * DK + f4 * 4], &A[(size_t)gr * DK + f4 * 4]);
            }
            cp_commit();
            asm volatile("cp.async.wait_group 1;\n");
        } else {
            asm volatile("cp.async.wait_group 0;\n");
        }
        __syncthreads();

        // ---- 128x128 fp32 GEMM tile, 8x8 register blocking ----
        const float* Ab = Abuf + buf * TM * DK + (ty * 8) * DK;
        float acc[8][8];
        #pragma unroll
        for (int i = 0; i < 8; i++)
            #pragma unroll
            for (int j = 0; j < 8; j++) acc[i][j] = 0.f;

        #pragma unroll 2
        for (int d = 0; d < DK; d += 4) {
            float4 av[8];
            #pragma unroll
            for (int i = 0; i < 8; i++)
                av[i] = *(const float4*)&Ab[i * DK + d];
            #pragma unroll
            for (int dd = 0; dd < 4; dd++) {
                const float4 b0 = *(const float4*)&Wt[(d + dd) * WTS + tx * 8];
                const float4 b1 = *(const float4*)&Wt[(d + dd) * WTS + tx * 8 + 4];
                const float b[8] = {b0.x, b0.y, b0.z, b0.w, b1.x, b1.y, b1.z, b1.w};
                #pragma unroll
                for (int i = 0; i < 8; i++) {
                    const float a = (dd == 0) ? av[i].x : (dd == 1) ? av[i].y
                                  : (dd == 2) ? av[i].z : av[i].w;
                    #pragma unroll
                    for (int j = 0; j < 8; j++)
                        acc[i][j] = fmaf(a, b[j], acc[i][j]);
                }
            }
        }

        // ---- per-row argmin of (||w||^2 - 2 x.w), lowest-index tie-break ----
        #pragma unroll
        for (int i = 0; i < 8; i++) {
            float bv = fmaf(-2.f, acc[i][0], c2k[0]);
            int   bk = tx * 8;
            #pragma unroll
            for (int j = 1; j < 8; j++) {
                float v = fmaf(-2.f, acc[i][j], c2k[j]);
                if (v < bv) { bv = v; bk = tx * 8 + j; }
            }
            #pragma unroll
            for (int off = 1; off < 16; off <<= 1) {
                float ov = __shfl_xor_sync(0xffffffffu, bv, off);
                int   ok = __shfl_xor_sync(0xffffffffu, bk, off);
                if (ov < bv || (ov == bv && ok < bk)) { bv = ov; bk = ok; }
            }
            if (tx == 0) best[ty * 8 + i] = bk;
        }
        __syncthreads();

        // ---- gather W[best] and write both halves (z_q, emb) ----
        for (int i = tid; i < TM * 32; i += NT) {
            int r = i >> 5, f4 = i & 31;
            int gr = t * TM + r;
            if (gr < N) {
                int k = best[r];
                float4 v = Wg4[k * 32 + f4];
                O[(size_t)gr * 32 + f4]          = v;
                O[embOff + (size_t)gr * 32 + f4] = v;
            }
        }
        buf ^= 1;
        // next iteration's post-wait __syncthreads orders this output phase
        // against best[] overwrite; cp.async overwrite of 'buf^1' is ordered
        // by the pre-argmin sync two iterations back.
    }
}

extern "C" void kernel_launch(void* const* d_in, const int* in_sizes, int n_in,
                              void* d_out, int out_size) {
    const float* A = (const float*)d_in[0];
    const float* W = (const float*)d_in[1];
    int szA = in_sizes[0], szW = in_sizes[1];
    // Defensive: metadata order should be (z_g, W); swap if reversed.
    if (n_in >= 2 && szA < szW) {
        const float* tmp = A; A = W; W = tmp;
        int ts = szA; szA = szW; szW = ts;
    }
    const int N      = szA / DK;
    const int ntiles = (N + TM - 1) / TM;

    int dev = 0, sms = 148;
    cudaGetDevice(&dev);
    cudaDeviceGetAttribute(&sms, cudaDevAttrMultiProcessorCount, dev);

    cudaFuncSetAttribute(vq_kernel, cudaFuncAttributeMaxDynamicSharedMemorySize,
                         SMEM_BYTES);

    int grid = ntiles < sms ? ntiles : sms;
    vq_kernel<<<grid, NT, SMEM_BYTES>>>(A, W, (float*)d_out, N, ntiles);
}